// round 10
// baseline (speedup 1.0000x reference)
#include <cuda_runtime.h>

#define ROWS 84
#define SLEN 131072
#define BPR 16                    // blocks per row -> 1344 blocks
#define THREADS 256
#define CHUNK (SLEN / BPR)        // 8192 elements
#define ITERS (CHUNK / (THREADS * 4))  // 8 float4 iterations per thread
#define GRID (ROWS * BPR)

// scratch: per (row, chunk) partial sums for ST0-side and ST1-side
__device__ float g_partial[ROWS * BPR * 2];
__device__ unsigned int g_count = 0;

__device__ __forceinline__ float sigf(float x) {
    return __fdividef(1.0f, 1.0f + __expf(-x));
}

// thread t (< 84) computes entry t of the 84-long nested-product vector for
// softmax probs p[4], exact reference order:
// t = i*21 + r ; r==0 -> p_i ; else (r-1)=j*5+s ; s==0 -> p_i p_j ; else p_i p_j p_{s-1}
__device__ __forceinline__ float prob_entry(const float* p, int t) {
    int i = t / 21;
    int r = t - i * 21;
    if (r == 0) return p[i];
    r -= 1;
    int j = r / 5;
    int s = r - j * 5;
    float pij = p[i] * p[j];
    if (s == 0) return pij;
    return pij * p[s - 1];
}

__device__ __forceinline__ void softmax4(const float* __restrict__ l, float* p) {
    float mx = fmaxf(fmaxf(l[0], l[1]), fmaxf(l[2], l[3]));
    float e0 = __expf(l[0] - mx), e1 = __expf(l[1] - mx),
          e2 = __expf(l[2] - mx), e3 = __expf(l[3] - mx);
    float inv = __fdividef(1.0f, e0 + e1 + e2 + e3);
    p[0] = e0 * inv; p[1] = e1 * inv; p[2] = e2 * inv; p[3] = e3 * inv;
}

// acquire load (L1-bypass, ordered after the acq_rel ticket) — no fence needed
__device__ __forceinline__ float ld_acq(const float* p) {
    float v;
    asm volatile("ld.acquire.gpu.global.f32 %0, [%1];" : "=f"(v) : "l"(p) : "memory");
    return v;
}

__global__ __launch_bounds__(THREADS)
void fused_kernel(const float* __restrict__ ST0, const float* __restrict__ W0,
                  const float* __restrict__ ST1, const float* __restrict__ W1,
                  const float* __restrict__ BEV, const float* __restrict__ BEV_p,
                  const float* __restrict__ B,
                  const float* __restrict__ probs0, const float* __restrict__ probs1,
                  const float* __restrict__ probs2, const float* __restrict__ probs3,
                  const float* __restrict__ probs4,
                  float* __restrict__ out) {
    const int row = blockIdx.y;
    const int chunk = blockIdx.x;
    const float b = B[0];
    const float bb = b * (fmaxf(BEV_p[0], 0.0f) * BEV[0]);  // sig(b*st + bb)

    const size_t base = (size_t)row * SLEN + (size_t)chunk * CHUNK;
    const float4* st0 = (const float4*)(ST0 + base);
    const float4* w0  = (const float4*)(W0 + base);
    const float4* st1 = (const float4*)(ST1 + base);
    const float4* w1  = (const float4*)(W1 + base);

    float s0 = 0.0f, s1 = 0.0f;
    #pragma unroll
    for (int it = 0; it < ITERS; ++it) {
        const int idx = it * THREADS + threadIdx.x;
        float4 a0 = st0[idx];
        float4 c0 = w0[idx];
        float4 a1 = st1[idx];
        float4 c1 = w1[idx];
        s0 += sigf(fmaf(b, a0.x, bb)) * c0.x;
        s0 += sigf(fmaf(b, a0.y, bb)) * c0.y;
        s0 += sigf(fmaf(b, a0.z, bb)) * c0.z;
        s0 += sigf(fmaf(b, a0.w, bb)) * c0.w;
        s1 += sigf(fmaf(b, a1.x, bb)) * c1.x;
        s1 += sigf(fmaf(b, a1.y, bb)) * c1.y;
        s1 += sigf(fmaf(b, a1.z, bb)) * c1.z;
        s1 += sigf(fmaf(b, a1.w, bb)) * c1.w;
    }

    // block reduction of the two partial dot products
    #pragma unroll
    for (int o = 16; o > 0; o >>= 1) {
        s0 += __shfl_down_sync(0xFFFFFFFFu, s0, o);
        s1 += __shfl_down_sync(0xFFFFFFFFu, s1, o);
    }
    __shared__ float sh0[THREADS / 32], sh1[THREADS / 32];
    __shared__ bool is_last;
    const int warp = threadIdx.x >> 5, lane = threadIdx.x & 31;
    if (lane == 0) { sh0[warp] = s0; sh1[warp] = s1; }
    __syncthreads();
    if (threadIdx.x == 0) {
        float t0 = 0.0f, t1 = 0.0f;
        #pragma unroll
        for (int w = 0; w < THREADS / 32; ++w) { t0 += sh0[w]; t1 += sh1[w]; }
        const int slot = (row * BPR + chunk) * 2;
        g_partial[slot]     = t0;
        g_partial[slot + 1] = t1;
        // acq_rel ticket: releases the partial stores above, acquires for the
        // winner. No fence.gpu -> no CCTL.IVALL L1 flush on every block.
        unsigned int ticket;
        asm volatile("atom.add.acq_rel.gpu.global.u32 %0, [%1], 1;"
                     : "=r"(ticket) : "l"(&g_count) : "memory");
        is_last = (ticket == GRID - 1);
    }
    __syncthreads();
    if (!is_last) return;

    // ---- last block: finalize (parallel across 84 threads) ----
    const int t = threadIdx.x;
    float c = 0.0f;
    if (t < ROWS) {
        float a0 = 0.0f, a1 = 0.0f;
        #pragma unroll
        for (int k = 0; k < BPR; ++k) {
            const int slot = (t * BPR + k) * 2;
            a0 += ld_acq(&g_partial[slot]);
            a1 += ld_acq(&g_partial[slot + 1]);
        }
        float p[4];
        softmax4(probs0, p);
        c = prob_entry(p, t) * a0;
        float esum = 0.0f;
        softmax4(probs1, p); esum += prob_entry(p, t);
        softmax4(probs2, p); esum += prob_entry(p, t);
        softmax4(probs3, p); esum += prob_entry(p, t);
        softmax4(probs4, p); esum += prob_entry(p, t);
        c += esum * a1;
    }
    // block-reduce c over all 256 threads (threads >= 84 contribute 0)
    #pragma unroll
    for (int o = 16; o > 0; o >>= 1)
        c += __shfl_down_sync(0xFFFFFFFFu, c, o);
    if (lane == 0) sh0[warp] = c;
    __syncthreads();
    if (t == 0) {
        float acc = 0.0f;
        #pragma unroll
        for (int w = 0; w < THREADS / 32; ++w) acc += sh0[w];
        out[0] = acc * 0.2f;
        g_count = 0;   // reset for next graph replay
    }
}

extern "C" void kernel_launch(void* const* d_in, const int* in_sizes, int n_in,
                              void* d_out, int out_size) {
    const float* BEV   = (const float*)d_in[0];
    const float* ST0   = (const float*)d_in[1];
    const float* W0    = (const float*)d_in[2];
    const float* ST1   = (const float*)d_in[3];
    const float* W1    = (const float*)d_in[4];
    const float* p0    = (const float*)d_in[5];
    const float* p1    = (const float*)d_in[6];
    const float* p2    = (const float*)d_in[7];
    const float* p3    = (const float*)d_in[8];
    const float* p4    = (const float*)d_in[9];
    const float* BEV_p = (const float*)d_in[10];
    const float* B     = (const float*)d_in[11];
    float* out = (float*)d_out;

    dim3 grid(BPR, ROWS);
    fused_kernel<<<grid, THREADS>>>(ST0, W0, ST1, W1, BEV, BEV_p, B,
                                    p0, p1, p2, p3, p4, out);
}

// round 13
// speedup vs baseline: 1.1080x; 1.1080x over previous
#include <cuda_runtime.h>

#define ROWS 84
#define SLEN 131072
#define BPR 16                    // blocks per row -> 1344 worker blocks
#define THREADS 256
#define CHUNK (SLEN / BPR)        // 8192 elements
#define ITERS (CHUNK / (THREADS * 4))  // 8 float4 iterations per thread
#define GRID (ROWS * BPR)         // workers; +1 finalizer block

// scratch: per (row, chunk) partial sums for ST0-side and ST1-side
__device__ float g_partial[ROWS * BPR * 2];
__device__ unsigned int g_count = 0;

__device__ __forceinline__ float sigf(float x) {
    return __fdividef(1.0f, 1.0f + __expf(-x));
}

// thread t (< 84) computes entry t of the 84-long nested-product vector for
// softmax probs p[4], exact reference order:
// t = i*21 + r ; r==0 -> p_i ; else (r-1)=j*5+s ; s==0 -> p_i p_j ; else p_i p_j p_{s-1}
__device__ __forceinline__ float prob_entry(const float* p, int t) {
    int i = t / 21;
    int r = t - i * 21;
    if (r == 0) return p[i];
    r -= 1;
    int j = r / 5;
    int s = r - j * 5;
    float pij = p[i] * p[j];
    if (s == 0) return pij;
    return pij * p[s - 1];
}

__device__ __forceinline__ void softmax4(const float* __restrict__ l, float* p) {
    float mx = fmaxf(fmaxf(l[0], l[1]), fmaxf(l[2], l[3]));
    float e0 = __expf(l[0] - mx), e1 = __expf(l[1] - mx),
          e2 = __expf(l[2] - mx), e3 = __expf(l[3] - mx);
    float inv = __fdividef(1.0f, e0 + e1 + e2 + e3);
    p[0] = e0 * inv; p[1] = e1 * inv; p[2] = e2 * inv; p[3] = e3 * inv;
}

__global__ __launch_bounds__(THREADS)
void fused_kernel(const float* __restrict__ ST0, const float* __restrict__ W0,
                  const float* __restrict__ ST1, const float* __restrict__ W1,
                  const float* __restrict__ BEV, const float* __restrict__ BEV_p,
                  const float* __restrict__ B,
                  const float* __restrict__ probs0, const float* __restrict__ probs1,
                  const float* __restrict__ probs2, const float* __restrict__ probs3,
                  const float* __restrict__ probs4,
                  float* __restrict__ out) {
    const int bid = blockIdx.x;
    __shared__ float sh0[THREADS / 32], sh1[THREADS / 32];
    const int warp = threadIdx.x >> 5, lane = threadIdx.x & 31;

    if (bid == GRID) {
        // ---- dedicated finalizer block: the ONLY place with acquire semantics ----
        if (threadIdx.x == 0) {
            unsigned int v;
            do {
                asm volatile("ld.acquire.gpu.global.u32 %0, [%1];"
                             : "=r"(v) : "l"(&g_count) : "memory");
                if (v < GRID) __nanosleep(128);
            } while (v < GRID);
        }
        __syncthreads();   // all threads ordered after the acquire

        const int t = threadIdx.x;
        float c = 0.0f;
        if (t < ROWS) {
            float a0 = 0.0f, a1 = 0.0f;
            #pragma unroll
            for (int k = 0; k < BPR; ++k) {
                const int slot = (t * BPR + k) * 2;
                a0 += g_partial[slot];
                a1 += g_partial[slot + 1];
            }
            float p[4];
            softmax4(probs0, p);
            c = prob_entry(p, t) * a0;
            float esum = 0.0f;
            softmax4(probs1, p); esum += prob_entry(p, t);
            softmax4(probs2, p); esum += prob_entry(p, t);
            softmax4(probs3, p); esum += prob_entry(p, t);
            softmax4(probs4, p); esum += prob_entry(p, t);
            c += esum * a1;
        }
        #pragma unroll
        for (int o = 16; o > 0; o >>= 1)
            c += __shfl_down_sync(0xFFFFFFFFu, c, o);
        if (lane == 0) sh0[warp] = c;
        __syncthreads();
        if (t == 0) {
            float acc = 0.0f;
            #pragma unroll
            for (int w = 0; w < THREADS / 32; ++w) acc += sh0[w];
            out[0] = acc * 0.2f;
            g_count = 0;   // reset for next graph replay (visible at next launch)
        }
        return;
    }

    // ---- worker block: byte-identical streaming mainloop, release-only exit ----
    const int row = bid >> 4;           // bid / BPR
    const int chunk = bid & (BPR - 1);  // bid % BPR
    const float b = B[0];
    const float bb = b * (fmaxf(BEV_p[0], 0.0f) * BEV[0]);  // sig(b*st + bb)

    const size_t base = (size_t)row * SLEN + (size_t)chunk * CHUNK;
    const float4* st0 = (const float4*)(ST0 + base);
    const float4* w0  = (const float4*)(W0 + base);
    const float4* st1 = (const float4*)(ST1 + base);
    const float4* w1  = (const float4*)(W1 + base);

    float s0 = 0.0f, s1 = 0.0f;
    #pragma unroll
    for (int it = 0; it < ITERS; ++it) {
        const int idx = it * THREADS + threadIdx.x;
        float4 a0 = st0[idx];
        float4 c0 = w0[idx];
        float4 a1 = st1[idx];
        float4 c1 = w1[idx];
        s0 += sigf(fmaf(b, a0.x, bb)) * c0.x;
        s0 += sigf(fmaf(b, a0.y, bb)) * c0.y;
        s0 += sigf(fmaf(b, a0.z, bb)) * c0.z;
        s0 += sigf(fmaf(b, a0.w, bb)) * c0.w;
        s1 += sigf(fmaf(b, a1.x, bb)) * c1.x;
        s1 += sigf(fmaf(b, a1.y, bb)) * c1.y;
        s1 += sigf(fmaf(b, a1.z, bb)) * c1.z;
        s1 += sigf(fmaf(b, a1.w, bb)) * c1.w;
    }

    #pragma unroll
    for (int o = 16; o > 0; o >>= 1) {
        s0 += __shfl_down_sync(0xFFFFFFFFu, s0, o);
        s1 += __shfl_down_sync(0xFFFFFFFFu, s1, o);
    }
    if (lane == 0) { sh0[warp] = s0; sh1[warp] = s1; }
    __syncthreads();
    if (threadIdx.x == 0) {
        float t0 = 0.0f, t1 = 0.0f;
        #pragma unroll
        for (int w = 0; w < THREADS / 32; ++w) { t0 += sh0[w]; t1 += sh1[w]; }
        const int slot = (row * BPR + chunk) * 2;
        g_partial[slot]     = t0;
        g_partial[slot + 1] = t1;
        // release-only increment: orders the two stores above, NO acquire,
        // no L1 invalidate, no return value (REDG).
        asm volatile("red.release.gpu.global.add.u32 [%0], %1;"
                     :: "l"(&g_count), "r"(1u) : "memory");
    }
}

extern "C" void kernel_launch(void* const* d_in, const int* in_sizes, int n_in,
                              void* d_out, int out_size) {
    const float* BEV   = (const float*)d_in[0];
    const float* ST0   = (const float*)d_in[1];
    const float* W0    = (const float*)d_in[2];
    const float* ST1   = (const float*)d_in[3];
    const float* W1    = (const float*)d_in[4];
    const float* p0    = (const float*)d_in[5];
    const float* p1    = (const float*)d_in[6];
    const float* p2    = (const float*)d_in[7];
    const float* p3    = (const float*)d_in[8];
    const float* p4    = (const float*)d_in[9];
    const float* BEV_p = (const float*)d_in[10];
    const float* B     = (const float*)d_in[11];
    float* out = (float*)d_out;

    fused_kernel<<<GRID + 1, THREADS>>>(ST0, W0, ST1, W1, BEV, BEV_p, B,
                                        p0, p1, p2, p3, p4, out);
}

// round 14
// speedup vs baseline: 1.1634x; 1.0500x over previous
#include <cuda_runtime.h>
#include <cstdint>

#define ROWS 84
#define SLEN 131072
#define BPR 8                     // blocks per row -> 672 worker blocks (single wave)
#define THREADS 256
#define CHUNK (SLEN / BPR)        // 16384 elements per array per block
#define SEG 1024                  // floats per array per pipeline stage
#define NSEG (CHUNK / SEG)        // 16 stages per block
#define NSTAGES 2                 // double buffer
#define SEG_BYTES (SEG * 4)       // 4096 B per array copy
#define STAGE_BYTES (4 * SEG_BYTES)  // 16384 B per stage (all 4 arrays)
#define GRID (ROWS * BPR)

// scratch: per (row, chunk) partial sums for ST0-side and ST1-side
__device__ float g_partial[ROWS * BPR * 2];
__device__ unsigned int g_count = 0;

__device__ __forceinline__ float sigf(float x) {
    return __fdividef(1.0f, 1.0f + __expf(-x));
}

__device__ __forceinline__ uint32_t smem_u32(const void* p) {
    uint32_t a;
    asm("{ .reg .u64 t; cvta.to.shared.u64 t, %1; cvt.u32.u64 %0, t; }"
        : "=r"(a) : "l"(p));
    return a;
}

__device__ __forceinline__ void mbar_init(uint32_t addr, uint32_t count) {
    asm volatile("mbarrier.init.shared.b64 [%0], %1;" :: "r"(addr), "r"(count) : "memory");
}

__device__ __forceinline__ void mbar_expect_tx(uint32_t addr, uint32_t bytes) {
    asm volatile("mbarrier.arrive.expect_tx.shared.b64 _, [%0], %1;"
                 :: "r"(addr), "r"(bytes) : "memory");
}

__device__ __forceinline__ void bulk_g2s(uint32_t dst, const void* src,
                                         uint32_t bytes, uint32_t mbar) {
    asm volatile(
        "cp.async.bulk.shared::cluster.global.mbarrier::complete_tx::bytes "
        "[%0], [%1], %2, [%3];"
        :: "r"(dst), "l"(src), "r"(bytes), "r"(mbar) : "memory");
}

__device__ __forceinline__ void mbar_wait(uint32_t addr, uint32_t parity) {
    asm volatile(
        "{\n\t"
        ".reg .pred P1;\n\t"
        "WAIT_LOOP_%=:\n\t"
        "mbarrier.try_wait.parity.acquire.cta.shared::cta.b64 P1, [%0], %1, 0x989680;\n\t"
        "@P1 bra.uni WAIT_DONE_%=;\n\t"
        "bra.uni WAIT_LOOP_%=;\n\t"
        "WAIT_DONE_%=:\n\t"
        "}"
        :: "r"(addr), "r"(parity) : "memory");
}

// thread t (< 84): entry t of the 84-long nested-product vector, reference order
__device__ __forceinline__ float prob_entry(const float* p, int t) {
    int i = t / 21;
    int r = t - i * 21;
    if (r == 0) return p[i];
    r -= 1;
    int j = r / 5;
    int s = r - j * 5;
    float pij = p[i] * p[j];
    if (s == 0) return pij;
    return pij * p[s - 1];
}

__device__ __forceinline__ void softmax4(const float* __restrict__ l, float* p) {
    float mx = fmaxf(fmaxf(l[0], l[1]), fmaxf(l[2], l[3]));
    float e0 = __expf(l[0] - mx), e1 = __expf(l[1] - mx),
          e2 = __expf(l[2] - mx), e3 = __expf(l[3] - mx);
    float inv = __fdividef(1.0f, e0 + e1 + e2 + e3);
    p[0] = e0 * inv; p[1] = e1 * inv; p[2] = e2 * inv; p[3] = e3 * inv;
}

__global__ __launch_bounds__(THREADS)
void fused_kernel(const float* __restrict__ ST0, const float* __restrict__ W0,
                  const float* __restrict__ ST1, const float* __restrict__ W1,
                  const float* __restrict__ BEV, const float* __restrict__ BEV_p,
                  const float* __restrict__ B,
                  const float* __restrict__ probs0, const float* __restrict__ probs1,
                  const float* __restrict__ probs2, const float* __restrict__ probs3,
                  const float* __restrict__ probs4,
                  float* __restrict__ out) {
    __shared__ __align__(128) float buf[NSTAGES][4][SEG];   // 32 KB
    __shared__ uint64_t mbar[NSTAGES];
    __shared__ float sh0[THREADS / 32], sh1[THREADS / 32];

    const int bid = blockIdx.x;
    const int tid = threadIdx.x;
    const int warp = tid >> 5, lane = tid & 31;

    if (bid == GRID) {
        // ---- dedicated finalizer block (only acquire site) ----
        if (tid == 0) {
            unsigned int v;
            do {
                asm volatile("ld.acquire.gpu.global.u32 %0, [%1];"
                             : "=r"(v) : "l"(&g_count) : "memory");
                if (v < GRID) __nanosleep(128);
            } while (v < GRID);
        }
        __syncthreads();
        float c = 0.0f;
        if (tid < ROWS) {
            float a0 = 0.0f, a1 = 0.0f;
            #pragma unroll
            for (int k = 0; k < BPR; ++k) {
                const int slot = (tid * BPR + k) * 2;
                a0 += g_partial[slot];
                a1 += g_partial[slot + 1];
            }
            float p[4];
            softmax4(probs0, p);
            c = prob_entry(p, tid) * a0;
            float esum = 0.0f;
            softmax4(probs1, p); esum += prob_entry(p, tid);
            softmax4(probs2, p); esum += prob_entry(p, tid);
            softmax4(probs3, p); esum += prob_entry(p, tid);
            softmax4(probs4, p); esum += prob_entry(p, tid);
            c += esum * a1;
        }
        #pragma unroll
        for (int o = 16; o > 0; o >>= 1)
            c += __shfl_down_sync(0xFFFFFFFFu, c, o);
        if (lane == 0) sh0[warp] = c;
        __syncthreads();
        if (tid == 0) {
            float acc = 0.0f;
            #pragma unroll
            for (int w = 0; w < THREADS / 32; ++w) acc += sh0[w];
            out[0] = acc * 0.2f;
            g_count = 0;   // reset for next graph replay
        }
        return;
    }

    // ---- worker block: 2-stage cp.async.bulk pipeline ----
    const int row = bid >> 3;           // bid / BPR
    const int chunk = bid & (BPR - 1);  // bid % BPR
    const float b = B[0];
    const float bb = b * (fmaxf(BEV_p[0], 0.0f) * BEV[0]);  // sig(b*st + bb)

    const size_t base = (size_t)row * SLEN + (size_t)chunk * CHUNK;
    const float* g[4] = {ST0 + base, W0 + base, ST1 + base, W1 + base};

    const uint32_t buf_a  = smem_u32(&buf[0][0][0]);
    const uint32_t mbar_a = smem_u32(&mbar[0]);

    if (tid == 0) {
        mbar_init(mbar_a, 1);
        mbar_init(mbar_a + 8, 1);
    }
    __syncthreads();

    // prologue: issue stages 0, 1
    if (tid == 0) {
        #pragma unroll
        for (int k = 0; k < NSTAGES; ++k) {
            const uint32_t mb = mbar_a + k * 8;
            const uint32_t d  = buf_a + k * STAGE_BYTES;
            mbar_expect_tx(mb, STAGE_BYTES);
            #pragma unroll
            for (int a = 0; a < 4; ++a)
                bulk_g2s(d + a * SEG_BYTES, g[a] + (size_t)k * SEG, SEG_BYTES, mb);
        }
    }

    float s0 = 0.0f, s1 = 0.0f;
    for (int k = 0; k < NSEG; ++k) {
        const int slot = k & 1;
        mbar_wait(mbar_a + slot * 8, (k >> 1) & 1);

        const float4* bs = (const float4*)&buf[slot][0][0];
        float4 a0 = bs[0 * (SEG / 4) + tid];
        float4 c0 = bs[1 * (SEG / 4) + tid];
        float4 a1 = bs[2 * (SEG / 4) + tid];
        float4 c1 = bs[3 * (SEG / 4) + tid];
        s0 += sigf(fmaf(b, a0.x, bb)) * c0.x;
        s0 += sigf(fmaf(b, a0.y, bb)) * c0.y;
        s0 += sigf(fmaf(b, a0.z, bb)) * c0.z;
        s0 += sigf(fmaf(b, a0.w, bb)) * c0.w;
        s1 += sigf(fmaf(b, a1.x, bb)) * c1.x;
        s1 += sigf(fmaf(b, a1.y, bb)) * c1.y;
        s1 += sigf(fmaf(b, a1.z, bb)) * c1.z;
        s1 += sigf(fmaf(b, a1.w, bb)) * c1.w;

        __syncthreads();   // all values consumed -> slot free for refill
        if (tid == 0 && k + NSTAGES < NSEG) {
            const int kn = k + NSTAGES;
            const uint32_t mb = mbar_a + slot * 8;
            const uint32_t d  = buf_a + slot * STAGE_BYTES;
            mbar_expect_tx(mb, STAGE_BYTES);
            #pragma unroll
            for (int a = 0; a < 4; ++a)
                bulk_g2s(d + a * SEG_BYTES, g[a] + (size_t)kn * SEG, SEG_BYTES, mb);
        }
    }

    // block reduction of the two partial dot products
    #pragma unroll
    for (int o = 16; o > 0; o >>= 1) {
        s0 += __shfl_down_sync(0xFFFFFFFFu, s0, o);
        s1 += __shfl_down_sync(0xFFFFFFFFu, s1, o);
    }
    if (lane == 0) { sh0[warp] = s0; sh1[warp] = s1; }
    __syncthreads();
    if (tid == 0) {
        float t0 = 0.0f, t1 = 0.0f;
        #pragma unroll
        for (int w = 0; w < THREADS / 32; ++w) { t0 += sh0[w]; t1 += sh1[w]; }
        const int slot = (row * BPR + chunk) * 2;
        g_partial[slot]     = t0;
        g_partial[slot + 1] = t1;
        // release-only increment: orders the stores above, no L1 invalidate
        asm volatile("red.release.gpu.global.add.u32 [%0], %1;"
                     :: "l"(&g_count), "r"(1u) : "memory");
    }
}

extern "C" void kernel_launch(void* const* d_in, const int* in_sizes, int n_in,
                              void* d_out, int out_size) {
    const float* BEV   = (const float*)d_in[0];
    const float* ST0   = (const float*)d_in[1];
    const float* W0    = (const float*)d_in[2];
    const float* ST1   = (const float*)d_in[3];
    const float* W1    = (const float*)d_in[4];
    const float* p0    = (const float*)d_in[5];
    const float* p1    = (const float*)d_in[6];
    const float* p2    = (const float*)d_in[7];
    const float* p3    = (const float*)d_in[8];
    const float* p4    = (const float*)d_in[9];
    const float* BEV_p = (const float*)d_in[10];
    const float* B     = (const float*)d_in[11];
    float* out = (float*)d_out;

    fused_kernel<<<GRID + 1, THREADS>>>(ST0, W0, ST1, W1, BEV, BEV_p, B,
                                        p0, p1, p2, p3, p4, out);
}